// round 14
// baseline (speedup 1.0000x reference)
#include <cuda_runtime.h>
#include <cuda_fp16.h>
#include <cstdint>
#include <math.h>

#define T_TOK 6304
#define DMODEL 768
#define NEXP 16
#define TM 128
#define TN 64
#define NBLK (DMODEL / TN)           // 12
#define KSTEP 32                     // halfs per stage
#define NSTAGE (DMODEL / KSTEP)      // 24
#define MAX_TILES 128
#define GATE_BLOCKS (T_TOK / 8)      // 788
#define NW8 (NEXP * DMODEL * DMODEL / 8)
#define CVT_BLOCKS (2 * NW8 / 256)   // 9216
#define PERSIST_CTAS 444             // 148 SMs x 3

#define SLOT_A 8192                  // A stage slot: 128 rows x 64 B
#define SLOT_BB 4096                 // B stage slot: 64 rows x 64 B
#define RING_OFF 2048
#define SMEM_BYTES (RING_OFF + 4 * SLOT_A + 4 * SLOT_BB)   // 51200
#define STG_STRIDE 68                // epilogue staging row stride (floats)

// ---------------- scratch (device globals; no allocations allowed) ----------
__device__ __half g_xh[T_TOK * DMODEL];
__device__ __half g_w1h[NEXP * DMODEL * DMODEL];
__device__ __half g_w2h[NEXP * DMODEL * DMODEL];
__device__ __half g_hidden[T_TOK * DMODEL];
__device__ int    g_idx[T_TOK];
__device__ int    g_counts[NEXP];     // zeroed at end of each run (GEMM kernel)
__device__ int    g_cursor2[NEXP];    // zeroed at end of each run (GEMM kernel)
__device__ int    g_off[NEXP + 1];
__device__ int    g_perm[T_TOK];
__device__ int    g_tile_e[MAX_TILES];
__device__ int    g_tile_row[MAX_TILES];
__device__ int    g_ntiles;
__device__ int    g_jobctr;           // zeroed by scatter each run
__device__ int    g_done[MAX_TILES];  // zeroed by scatter each run

// ---------------- helpers ----------------------------------------------------
__device__ __forceinline__ void ldsm4(uint32_t* r, uint32_t addr) {
    asm volatile("ldmatrix.sync.aligned.m8n8.x4.shared.b16 {%0,%1,%2,%3}, [%4];"
                 : "=r"(r[0]), "=r"(r[1]), "=r"(r[2]), "=r"(r[3]) : "r"(addr));
}
__device__ __forceinline__ void mma_f16(float* c, const uint32_t* a, const uint32_t* b) {
    asm volatile(
        "mma.sync.aligned.m16n8k16.row.col.f32.f16.f16.f32 "
        "{%0,%1,%2,%3}, {%4,%5,%6,%7}, {%8,%9}, {%0,%1,%2,%3};"
        : "+f"(c[0]), "+f"(c[1]), "+f"(c[2]), "+f"(c[3])
        : "r"(a[0]), "r"(a[1]), "r"(a[2]), "r"(a[3]), "r"(b[0]), "r"(b[1]));
}
__device__ __forceinline__ void cpa16(uint32_t dst, const void* src, int srcsize) {
    asm volatile("cp.async.cg.shared.global [%0], [%1], 16, %2;"
                 :: "r"(dst), "l"(src), "r"(srcsize) : "memory");
}
#define CP_COMMIT() asm volatile("cp.async.commit_group;" ::: "memory")
#define CP_WAIT2()  asm volatile("cp.async.wait_group 2;" ::: "memory")
#define CP_WAIT0()  asm volatile("cp.async.wait_group 0;" ::: "memory")

__device__ __forceinline__ uint32_t swz_off(int row, int c) {
    return (uint32_t)(row * 64 + ((c ^ ((row >> 1) & 3)) << 4));
}

// ---------------- weight convert: no smem, full occupancy, pure streaming ----
__global__ void cvtw_kernel(const float* __restrict__ W1, const float* __restrict__ W2) {
    int i = blockIdx.x * 256 + threadIdx.x;
    const float* src; __half* dst; int j;
    if (i < NW8) { src = W1; dst = g_w1h; j = i; }
    else         { src = W2; dst = g_w2h; j = i - NW8; }
    const float4* s = (const float4*)src + 2 * (size_t)j;
    float4 a = s[0], b = s[1];
    __half2 h0 = __floats2half2_rn(a.x, a.y), h1 = __floats2half2_rn(a.z, a.w);
    __half2 h2 = __floats2half2_rn(b.x, b.y), h3 = __floats2half2_rn(b.z, b.w);
    ((uint4*)dst)[j] = make_uint4(*(uint32_t*)&h0, *(uint32_t*)&h1,
                                  *(uint32_t*)&h2, *(uint32_t*)&h3);
}

// ---------------- gate: logits/argmax/counts + x -> fp16 ---------------------
__global__ void gate_kernel(const float* __restrict__ x,
                            const float* __restrict__ Wg,
                            const float* __restrict__ bg) {
    __shared__ float wgs[NEXP * DMODEL];
    int tid = threadIdx.x;
    for (int i = tid; i < NEXP * DMODEL; i += 256) wgs[i] = Wg[i];
    __syncthreads();

    int w = tid >> 5, l = tid & 31;
    int t = blockIdx.x * 8 + w;
    {
        const float* xr = x + (size_t)t * DMODEL;
        float xv[24];
        #pragma unroll
        for (int j = 0; j < 24; j++) xv[j] = xr[l + 32 * j];
        float best = -1e30f; int bi = 0;
        #pragma unroll 1
        for (int e = 0; e < NEXP; e++) {
            float s = 0.f;
            const float* wr = wgs + e * DMODEL + l;
            #pragma unroll
            for (int j = 0; j < 24; j++) s += xv[j] * wr[32 * j];
            #pragma unroll
            for (int o = 16; o; o >>= 1) s += __shfl_xor_sync(0xffffffffu, s, o);
            s += bg[e];
            if (s > best) { best = s; bi = e; }   // strict > : first max (jnp.argmax)
        }
        if (l == 0) { g_idx[t] = bi; atomicAdd(&g_counts[bi], 1); }
    }
    size_t base = (size_t)blockIdx.x * 8 * DMODEL / 8;
    #pragma unroll
    for (int j = 0; j < 3; j++) {
        size_t idx = base + tid + 256 * j;
        const float4* s = (const float4*)x + 2 * idx;
        float4 a = s[0], b = s[1];
        __half2 h0 = __floats2half2_rn(a.x, a.y), h1 = __floats2half2_rn(a.z, a.w);
        __half2 h2 = __floats2half2_rn(b.x, b.y), h3 = __floats2half2_rn(b.z, b.w);
        ((uint4*)g_xh)[idx] = make_uint4(*(uint32_t*)&h0, *(uint32_t*)&h1,
                                         *(uint32_t*)&h2, *(uint32_t*)&h3);
    }
}

// ---------------- scatter (absorbs scan; resets GEMM-side state) -------------
__global__ void scatter_kernel() {
    __shared__ int s_off[NEXP];
    int tid = threadIdx.x;
    if (tid == 0) {
        int off = 0;
        #pragma unroll
        for (int e = 0; e < NEXP; e++) { s_off[e] = off; off += g_counts[e]; }
    }
    __syncthreads();
    int t = blockIdx.x * 256 + tid;
    if (t < T_TOK) {
        int e = g_idx[t];
        int p = s_off[e] + atomicAdd(&g_cursor2[e], 1);
        g_perm[p] = t;
    }
    if (blockIdx.x == 0) {
        if (tid == 0) {
            int off = 0, nt = 0;
            for (int e = 0; e < NEXP; e++) {
                g_off[e] = off;
                int c = g_counts[e];
                for (int r = 0; r < c; r += TM) { g_tile_e[nt] = e; g_tile_row[nt] = off + r; nt++; }
                off += c;
            }
            g_off[NEXP] = off;
            g_ntiles = nt;
            g_jobctr = 0;
        }
        if (tid < MAX_TILES) g_done[tid] = 0;
    }
}

// ---------------- fused persistent grouped GEMM ------------------------------
// jobs (tile-major): [0, 12*nt)   phase1: hidden = fp16(GELU(xh@W1^T + b1))
//                    [12nt, 24nt) phase2: out    = hidden@W2^T + b2
__global__ void __launch_bounds__(256, 3)
mlp_fused(const float* __restrict__ b1, const float* __restrict__ b2,
          float* __restrict__ out)
{
    extern __shared__ char sm[];
    float* bias_s = (float*)sm;
    int* s_jid = (int*)(sm + 1024);
    char* ring = sm + RING_OFF;
    uint32_t ring_s = (uint32_t)__cvta_generic_to_shared(ring);
    float* stg = (float*)ring;

    int tid = threadIdx.x;
    int wid = tid >> 5, lane = tid & 31;
    int wr = wid & 3, wc = wid >> 2;
    int lrow = lane >> 2, lcol = lane & 3;
    int lq = lane >> 3, lr = lane & 7;
    int a_row = wr * 32 + (lq & 1) * 8 + lr;
    int a_cb  = lq >> 1;
    int b_row = wc * 32 + (lq >> 1) * 8 + lr;
    int b_cb  = lq & 1;
    int c = tid & 3;
    int r0 = tid >> 2, r1 = r0 + 64;

    // reset inter-run state (nothing in this kernel reads these)
    if (blockIdx.x == 0 && tid < NEXP) { g_counts[tid] = 0; g_cursor2[tid] = 0; }

    int ntiles = g_ntiles;
    int per = NBLK * ntiles;
    int total = 2 * per;

    for (;;) {
        if (tid == 0) *s_jid = atomicAdd(&g_jobctr, 1);
        __syncthreads();
        int jid = *s_jid;
        __syncthreads();
        if (jid >= total) break;

        int phase = (jid < per) ? 1 : 2;
        int jj = (phase == 1) ? jid : jid - per;
        int tile = jj / NBLK, nb = jj - tile * NBLK;
        int e = g_tile_e[tile];
        int row0 = g_tile_row[tile];
        int rend = g_off[e + 1];
        int n0 = nb * TN;

        // phase2: wait for this tile's 12 hidden slabs
        if (phase == 2) {
            if (tid == 0) {
                while (atomicAdd(&g_done[tile], 0) < NBLK) __nanosleep(64);
            }
            __syncthreads();
            __threadfence();   // acquire: hidden writes now visible
        }

        const float* bias = (phase == 1) ? b1 : b2;
        if (tid < TN) bias_s[tid] = bias[(size_t)e * DMODEL + n0 + tid];

        // loader sources
        const __half* Ax = (phase == 1) ? g_xh : g_hidden;
        const __half* W  = (phase == 1) ? g_w1h : g_w2h;
        const __half* asrc[2]; int asz[2];
        const __half* bsrc;
        uint32_t aoff[2], boff;
        {
            int rr[2] = {r0, r1};
            #pragma unroll
            for (int j = 0; j < 2; j++) {
                int ar = row0 + rr[j];
                bool v = ar < rend;
                int srow;
                if (phase == 1) srow = v ? g_perm[ar] : 0;
                else            srow = v ? ar : 0;
                asrc[j] = Ax + (size_t)srow * DMODEL + c * 8;
                asz[j] = v ? 16 : 0;
                aoff[j] = swz_off(rr[j], c);
            }
            bsrc = W + (size_t)e * DMODEL * DMODEL + (size_t)(n0 + r0) * DMODEL + c * 8;
            boff = swz_off(r0, c);
        }

        float acc[2][4][4];
        #pragma unroll
        for (int mm = 0; mm < 2; mm++)
            #pragma unroll
            for (int nn = 0; nn < 4; nn++)
                #pragma unroll
                for (int j = 0; j < 4; j++) acc[mm][nn][j] = 0.f;

        // prologue: stages 0,1,2 in flight
        #pragma unroll
        for (int s = 0; s < 3; s++) {
            uint32_t aslot = ring_s + s * SLOT_A;
            uint32_t bslot = ring_s + 4 * SLOT_A + s * SLOT_BB;
            int ko = s * KSTEP;
            cpa16(aslot + aoff[0], asrc[0] + ko, asz[0]);
            cpa16(aslot + aoff[1], asrc[1] + ko, asz[1]);
            cpa16(bslot + boff, bsrc + ko, 16);
            CP_COMMIT();
        }

        // mainloop
        #pragma unroll 1
        for (int s = 0; s < NSTAGE; s++) {
            CP_WAIT2();
            __syncthreads();
            if (s + 3 < NSTAGE) {
                int sn = s + 3;
                uint32_t aslot = ring_s + (sn & 3) * SLOT_A;
                uint32_t bslot = ring_s + 4 * SLOT_A + (sn & 3) * SLOT_BB;
                int ko = sn * KSTEP;
                cpa16(aslot + aoff[0], asrc[0] + ko, asz[0]);
                cpa16(aslot + aoff[1], asrc[1] + ko, asz[1]);
                cpa16(bslot + boff, bsrc + ko, 16);
            }
            CP_COMMIT();

            uint32_t As = ring_s + (s & 3) * SLOT_A;
            uint32_t Bs = ring_s + 4 * SLOT_A + (s & 3) * SLOT_BB;
            #pragma unroll
            for (int kk = 0; kk < 2; kk++) {
                uint32_t af[2][4];
                #pragma unroll
                for (int mm = 0; mm < 2; mm++)
                    ldsm4(af[mm], As + swz_off(a_row + mm * 16, a_cb + kk * 2));
                uint32_t bf[2][4];
                #pragma unroll
                for (int np = 0; np < 2; np++)
                    ldsm4(bf[np], Bs + swz_off(b_row + np * 16, b_cb + kk * 2));
                #pragma unroll
                for (int np = 0; np < 2; np++) {
                    mma_f16(acc[0][2 * np],     af[0], &bf[np][0]);
                    mma_f16(acc[1][2 * np],     af[1], &bf[np][0]);
                    mma_f16(acc[0][2 * np + 1], af[0], &bf[np][2]);
                    mma_f16(acc[1][2 * np + 1], af[1], &bf[np][2]);
                }
            }
        }
        CP_WAIT0();
        __syncthreads();

        // epilogue: bias (+GELU) -> staging -> coalesced writeout
        #pragma unroll
        for (int mm = 0; mm < 2; mm++) {
            #pragma unroll
            for (int nn = 0; nn < 4; nn++) {
                int col = wc * 32 + nn * 8 + 2 * lcol;
                int row = wr * 32 + mm * 16 + lrow;
                float bb0 = bias_s[col], bb1 = bias_s[col + 1];
                float v0 = acc[mm][nn][0] + bb0, v1 = acc[mm][nn][1] + bb1;
                float v2 = acc[mm][nn][2] + bb0, v3 = acc[mm][nn][3] + bb1;
                if (phase == 1) {
                    v0 = 0.5f * v0 * (1.0f + erff(v0 * 0.70710678118654752f));
                    v1 = 0.5f * v1 * (1.0f + erff(v1 * 0.70710678118654752f));
                    v2 = 0.5f * v2 * (1.0f + erff(v2 * 0.70710678118654752f));
                    v3 = 0.5f * v3 * (1.0f + erff(v3 * 0.70710678118654752f));
                }
                *(float2*)(stg + row * STG_STRIDE + col) = make_float2(v0, v1);
                *(float2*)(stg + (row + 8) * STG_STRIDE + col) = make_float2(v2, v3);
            }
        }
        __syncthreads();
        {
            int rloc = tid >> 1, q = tid & 1;
            int gr = row0 + rloc;
            if (gr < rend) {
                const float* srow = stg + rloc * STG_STRIDE + q * 32;
                if (phase == 1) {
                    __half* dst = g_hidden + (size_t)gr * DMODEL + n0 + q * 32;
                    #pragma unroll
                    for (int j = 0; j < 4; j++) {
                        float4 aa = ((const float4*)srow)[2 * j];
                        float4 bb = ((const float4*)srow)[2 * j + 1];
                        __half2 h0 = __floats2half2_rn(aa.x, aa.y);
                        __half2 h1 = __floats2half2_rn(aa.z, aa.w);
                        __half2 h2 = __floats2half2_rn(bb.x, bb.y);
                        __half2 h3 = __floats2half2_rn(bb.z, bb.w);
                        ((uint4*)dst)[j] = make_uint4(*(uint32_t*)&h0, *(uint32_t*)&h1,
                                                      *(uint32_t*)&h2, *(uint32_t*)&h3);
                    }
                } else {
                    float* dst = out + (size_t)g_perm[gr] * DMODEL + n0 + q * 32;
                    #pragma unroll
                    for (int j = 0; j < 8; j++)
                        ((float4*)dst)[j] = ((const float4*)srow)[j];
                }
            }
        }
        // release: signal hidden slab complete
        if (phase == 1) {
            __threadfence();
            __syncthreads();
            if (tid == 0) atomicAdd(&g_done[tile], 1);
        }
        __syncthreads();   // staging/bias reuse safe for next job
    }
}

// ---------------- launch -----------------------------------------------------
extern "C" void kernel_launch(void* const* d_in, const int* in_sizes, int n_in,
                              void* d_out, int out_size) {
    const float* x  = (const float*)d_in[0];
    const float* W1 = (const float*)d_in[1];
    const float* b1 = (const float*)d_in[2];
    const float* W2 = (const float*)d_in[3];
    const float* b2 = (const float*)d_in[4];
    const float* Wg = (const float*)d_in[5];
    const float* bg = (const float*)d_in[6];
    float* out = (float*)d_out;

    cudaFuncSetAttribute(mlp_fused, cudaFuncAttributeMaxDynamicSharedMemorySize, SMEM_BYTES);

    gate_kernel<<<GATE_BLOCKS, 256>>>(x, Wg, bg);
    cvtw_kernel<<<CVT_BLOCKS, 256>>>(W1, W2);
    scatter_kernel<<<(T_TOK + 255) / 256, 256>>>();
    mlp_fused<<<PERSIST_CTAS, 256, SMEM_BYTES>>>(b1, b2, out);
}

// round 16
// speedup vs baseline: 1.0134x; 1.0134x over previous
#include <cuda_runtime.h>
#include <cuda_fp16.h>
#include <cstdint>
#include <math.h>

#define T_TOK 6304
#define DMODEL 768
#define NEXP 16
#define TM 128
#define TN 64
#define NBLK (DMODEL / TN)           // 12
#define KSTEP 32
#define NSTAGE (DMODEL / KSTEP)      // 24
#define MAX_TILES 128
#define PERSIST_CTAS 444             // 148 SMs x 3

#define NW8 (NEXP * DMODEL * DMODEL / 8)   // 1179648 half8 per weight tensor
#define NJ_GATE 788                  // 8 tokens per job
#define NJ_W1   288                  // 4096 half8 chunks per job
#define NJ_SCAT 25
#define NJ_W2   288
#define NJ_P    (NBLK * MAX_TILES)   // 1536
// queue layout: [gate][W1][scan][scatter][W2][P1][P2]
#define J_W1_0  (NJ_GATE)                     // 788
#define J_SCAN  (J_W1_0 + NJ_W1)              // 1076
#define J_SCAT0 (J_SCAN + 1)                  // 1077
#define J_W2_0  (J_SCAT0 + NJ_SCAT)           // 1102
#define J_P1    (J_W2_0 + NJ_W2)              // 1390
#define J_P2    (J_P1 + NJ_P)                 // 2926
#define TOTAL_JOBS (J_P2 + NJ_P)              // 4462

#define SLOT_A 8192
#define SLOT_BB 4096
#define RING_OFF 2048
#define SMEM_BYTES (RING_OFF + 4 * SLOT_A + 4 * SLOT_BB)   // 51200 (ring = 49152 = Wg bytes)
#define STG_STRIDE 68

// ---------------- scratch (device globals; zero-init; reset by last CTA) -----
__device__ __half g_xh[T_TOK * DMODEL];
__device__ __half g_w1h[NEXP * DMODEL * DMODEL];
__device__ __half g_w2h[NEXP * DMODEL * DMODEL];
__device__ __half g_hidden[T_TOK * DMODEL];
__device__ int    g_idx[T_TOK];
__device__ int    g_counts[NEXP];
__device__ int    g_cursor2[NEXP];
__device__ int    g_off[NEXP + 1];
__device__ int    g_perm[T_TOK];
__device__ int    g_tile_e[MAX_TILES];
__device__ int    g_tile_row[MAX_TILES];
__device__ int    g_ntiles;
__device__ int    g_jobctr;
__device__ int    g_gatedone;
__device__ int    g_scandone;
__device__ int    g_scatterdone;
__device__ int    g_w1done;
__device__ int    g_w2done;
__device__ int    g_exit;
__device__ int    g_done[MAX_TILES];

// ---------------- helpers ----------------------------------------------------
__device__ __forceinline__ void ldsm4(uint32_t* r, uint32_t addr) {
    asm volatile("ldmatrix.sync.aligned.m8n8.x4.shared.b16 {%0,%1,%2,%3}, [%4];"
                 : "=r"(r[0]), "=r"(r[1]), "=r"(r[2]), "=r"(r[3]) : "r"(addr));
}
__device__ __forceinline__ void mma_f16(float* c, const uint32_t* a, const uint32_t* b) {
    asm volatile(
        "mma.sync.aligned.m16n8k16.row.col.f32.f16.f16.f32 "
        "{%0,%1,%2,%3}, {%4,%5,%6,%7}, {%8,%9}, {%0,%1,%2,%3};"
        : "+f"(c[0]), "+f"(c[1]), "+f"(c[2]), "+f"(c[3])
        : "r"(a[0]), "r"(a[1]), "r"(a[2]), "r"(a[3]), "r"(b[0]), "r"(b[1]));
}
__device__ __forceinline__ void cpa16(uint32_t dst, const void* src, int srcsize) {
    asm volatile("cp.async.cg.shared.global [%0], [%1], 16, %2;"
                 :: "r"(dst), "l"(src), "r"(srcsize) : "memory");
}
#define CP_COMMIT() asm volatile("cp.async.commit_group;" ::: "memory")
#define CP_WAIT2()  asm volatile("cp.async.wait_group 2;" ::: "memory")
#define CP_WAIT0()  asm volatile("cp.async.wait_group 0;" ::: "memory")

__device__ __forceinline__ uint32_t swz_off(int row, int c) {
    return (uint32_t)(row * 64 + ((c ^ ((row >> 1) & 3)) << 4));
}
__device__ __forceinline__ void cvt_chunk(const float* __restrict__ src,
                                          __half* __restrict__ dst, int idx) {
    const float4* s = (const float4*)src + 2 * (size_t)idx;
    float4 a = s[0], b = s[1];
    __half2 h0 = __floats2half2_rn(a.x, a.y), h1 = __floats2half2_rn(a.z, a.w);
    __half2 h2 = __floats2half2_rn(b.x, b.y), h3 = __floats2half2_rn(b.z, b.w);
    ((uint4*)dst)[idx] = make_uint4(*(uint32_t*)&h0, *(uint32_t*)&h1,
                                    *(uint32_t*)&h2, *(uint32_t*)&h3);
}

// ---------------- the megakernel ---------------------------------------------
__global__ void __launch_bounds__(256, 3)
mlp_mega(const float* __restrict__ x,  const float* __restrict__ W1,
         const float* __restrict__ b1, const float* __restrict__ W2,
         const float* __restrict__ b2, const float* __restrict__ Wg,
         const float* __restrict__ bg, float* __restrict__ out)
{
    extern __shared__ char sm[];
    float* bias_s = (float*)sm;
    int* s_jid = (int*)(sm + 1024);
    int* s_nt  = (int*)(sm + 1024) + 1;
    char* ring = sm + RING_OFF;
    uint32_t ring_s = (uint32_t)__cvta_generic_to_shared(ring);
    float* stg = (float*)ring;

    int tid = threadIdx.x;
    int wid = tid >> 5, lane = tid & 31;
    int wr = wid & 3, wc = wid >> 2;
    int lrow = lane >> 2, lcol = lane & 3;
    int lq = lane >> 3, lr = lane & 7;
    int a_row = wr * 32 + (lq & 1) * 8 + lr;
    int a_cb  = lq >> 1;
    int b_row = wc * 32 + (lq >> 1) * 8 + lr;
    int b_cb  = lq & 1;
    int c = tid & 3;
    int r0 = tid >> 2, r1 = r0 + 64;

    for (;;) {
        if (tid == 0) *s_jid = atomicAdd(&g_jobctr, 1);
        __syncthreads();
        int jid = *s_jid;
        __syncthreads();
        if (jid >= TOTAL_JOBS) break;

        // ============ gate jobs: 8 tokens, logits/argmax + x->fp16 ==========
        if (jid < J_W1_0) {
            int g = jid;
            float* wgs = (float*)ring;                 // 49152 B = NEXP*DMODEL*4
            #pragma unroll
            for (int j = 0; j < 12; j++)
                ((float4*)wgs)[tid + 256 * j] = ((const float4*)Wg)[tid + 256 * j];
            __syncthreads();

            int w = tid >> 5, l = tid & 31;
            int t = g * 8 + w;
            {
                const float* xr = x + (size_t)t * DMODEL;
                float xv[24];
                #pragma unroll
                for (int j = 0; j < 24; j++) xv[j] = xr[l + 32 * j];
                float best = -1e30f; int bi = 0;
                #pragma unroll 1
                for (int e = 0; e < NEXP; e++) {
                    float s = 0.f;
                    const float* wrp = wgs + e * DMODEL + l;
                    #pragma unroll
                    for (int j = 0; j < 24; j++) s += xv[j] * wrp[32 * j];
                    #pragma unroll
                    for (int o = 16; o; o >>= 1) s += __shfl_xor_sync(0xffffffffu, s, o);
                    s += bg[e];
                    if (s > best) { best = s; bi = e; }   // strict >: jnp.argmax
                }
                if (l == 0) { g_idx[t] = bi; atomicAdd(&g_counts[bi], 1); }
            }
            size_t base = (size_t)g * 8 * DMODEL / 8;
            #pragma unroll
            for (int j = 0; j < 3; j++)
                cvt_chunk(x, g_xh, (int)(base + tid + 256 * j));
            __threadfence();
            __syncthreads();
            if (tid == 0) atomicAdd(&g_gatedone, 1);
            continue;
        }

        // ============ W1 / W2 convert jobs (pure DRAM streaming) ============
        if (jid < J_SCAN || (jid >= J_W2_0 && jid < J_P1)) {
            bool isW1 = jid < J_SCAN;
            int j = isW1 ? jid - J_W1_0 : jid - J_W2_0;
            const float* src = isW1 ? W1 : W2;
            __half* dst = isW1 ? g_w1h : g_w2h;
            int base = j * 4096 + tid;
            #pragma unroll
            for (int it = 0; it < 16; it++)
                cvt_chunk(src, dst, base + it * 256);
            __threadfence();
            __syncthreads();
            if (tid == 0) atomicAdd(isW1 ? &g_w1done : &g_w2done, 1);
            continue;
        }

        // ============ scan job (single) =====================================
        if (jid == J_SCAN) {
            if (tid == 0) {
                while (atomicAdd(&g_gatedone, 0) < NJ_GATE) __nanosleep(128);
                __threadfence();
                int off = 0, nt = 0;
                for (int e = 0; e < NEXP; e++) {
                    g_off[e] = off;
                    int cnt = g_counts[e];
                    for (int r = 0; r < cnt; r += TM) {
                        g_tile_e[nt] = e; g_tile_row[nt] = off + r; nt++;
                    }
                    off += cnt;
                }
                g_off[NEXP] = off;
                g_ntiles = nt;
                __threadfence();
                atomicExch(&g_scandone, 1);
            }
            continue;
        }

        // ============ scatter jobs ==========================================
        if (jid < J_W2_0) {
            int sj = jid - J_SCAT0;
            if (tid == 0) {
                while (atomicAdd(&g_scandone, 0) == 0) __nanosleep(128);
            }
            __syncthreads();
            __threadfence();
            int t = sj * 256 + tid;
            if (t < T_TOK) {
                int e = g_idx[t];
                int p = g_off[e] + atomicAdd(&g_cursor2[e], 1);
                g_perm[p] = t;
            }
            __threadfence();
            __syncthreads();
            if (tid == 0) atomicAdd(&g_scatterdone, 1);
            continue;
        }

        // ============ GEMM jobs =============================================
        int phase = (jid < J_P2) ? 1 : 2;
        int jj = (phase == 1) ? jid - J_P1 : jid - J_P2;
        int tile = jj / NBLK, nb = jj - tile * NBLK;

        if (tid == 0) {
            if (phase == 1) {
                while (atomicAdd(&g_scatterdone, 0) < NJ_SCAT ||
                       atomicAdd(&g_w1done, 0) < NJ_W1) __nanosleep(128);
            } else {
                while (atomicAdd(&g_scatterdone, 0) < NJ_SCAT) __nanosleep(128);
            }
            *s_nt = g_ntiles;
        }
        __syncthreads();
        int ntiles = *s_nt;
        __syncthreads();
        if (tile >= ntiles) continue;

        if (phase == 2) {
            if (tid == 0) {
                while (atomicAdd(&g_done[tile], 0) < NBLK ||
                       atomicAdd(&g_w2done, 0) < NJ_W2) __nanosleep(64);
            }
            __syncthreads();
        }
        __threadfence();   // acquire: perm/weights/hidden visible

        int e = g_tile_e[tile];
        int row0 = g_tile_row[tile];
        int rend = g_off[e + 1];
        int n0 = nb * TN;

        const float* bias = (phase == 1) ? b1 : b2;
        if (tid < TN) bias_s[tid] = bias[(size_t)e * DMODEL + n0 + tid];

        const __half* Ax = (phase == 1) ? g_xh : g_hidden;
        const __half* W  = (phase == 1) ? g_w1h : g_w2h;
        const __half* asrc[2]; int asz[2];
        const __half* bsrc;
        uint32_t aoff[2], boff;
        {
            int rr[2] = {r0, r1};
            #pragma unroll
            for (int j = 0; j < 2; j++) {
                int ar = row0 + rr[j];
                bool v = ar < rend;
                int srow;
                if (phase == 1) srow = v ? g_perm[ar] : 0;
                else            srow = v ? ar : 0;
                asrc[j] = Ax + (size_t)srow * DMODEL + c * 8;
                asz[j] = v ? 16 : 0;
                aoff[j] = swz_off(rr[j], c);
            }
            bsrc = W + (size_t)e * DMODEL * DMODEL + (size_t)(n0 + r0) * DMODEL + c * 8;
            boff = swz_off(r0, c);
        }

        float acc[2][4][4];
        #pragma unroll
        for (int mm = 0; mm < 2; mm++)
            #pragma unroll
            for (int nn = 0; nn < 4; nn++)
                #pragma unroll
                for (int j = 0; j < 4; j++) acc[mm][nn][j] = 0.f;

        #pragma unroll
        for (int s = 0; s < 3; s++) {
            uint32_t aslot = ring_s + s * SLOT_A;
            uint32_t bslot = ring_s + 4 * SLOT_A + s * SLOT_BB;
            int ko = s * KSTEP;
            cpa16(aslot + aoff[0], asrc[0] + ko, asz[0]);
            cpa16(aslot + aoff[1], asrc[1] + ko, asz[1]);
            cpa16(bslot + boff, bsrc + ko, 16);
            CP_COMMIT();
        }

        #pragma unroll 1
        for (int s = 0; s < NSTAGE; s++) {
            CP_WAIT2();
            __syncthreads();
            if (s + 3 < NSTAGE) {
                int sn = s + 3;
                uint32_t aslot = ring_s + (sn & 3) * SLOT_A;
                uint32_t bslot = ring_s + 4 * SLOT_A + (sn & 3) * SLOT_BB;
                int ko = sn * KSTEP;
                cpa16(aslot + aoff[0], asrc[0] + ko, asz[0]);
                cpa16(aslot + aoff[1], asrc[1] + ko, asz[1]);
                cpa16(bslot + boff, bsrc + ko, 16);
            }
            CP_COMMIT();

            uint32_t As = ring_s + (s & 3) * SLOT_A;
            uint32_t Bs = ring_s + 4 * SLOT_A + (s & 3) * SLOT_BB;
            #pragma unroll
            for (int kk = 0; kk < 2; kk++) {
                uint32_t af[2][4];
                #pragma unroll
                for (int mm = 0; mm < 2; mm++)
                    ldsm4(af[mm], As + swz_off(a_row + mm * 16, a_cb + kk * 2));
                uint32_t bf[2][4];
                #pragma unroll
                for (int np = 0; np < 2; np++)
                    ldsm4(bf[np], Bs + swz_off(b_row + np * 16, b_cb + kk * 2));
                #pragma unroll
                for (int np = 0; np < 2; np++) {
                    mma_f16(acc[0][2 * np],     af[0], &bf[np][0]);
                    mma_f16(acc[1][2 * np],     af[1], &bf[np][0]);
                    mma_f16(acc[0][2 * np + 1], af[0], &bf[np][2]);
                    mma_f16(acc[1][2 * np + 1], af[1], &bf[np][2]);
                }
            }
        }
        CP_WAIT0();
        __syncthreads();

        #pragma unroll
        for (int mm = 0; mm < 2; mm++) {
            #pragma unroll
            for (int nn = 0; nn < 4; nn++) {
                int col = wc * 32 + nn * 8 + 2 * lcol;
                int row = wr * 32 + mm * 16 + lrow;
                float bb0 = bias_s[col], bb1 = bias_s[col + 1];
                float v0 = acc[mm][nn][0] + bb0, v1 = acc[mm][nn][1] + bb1;
                float v2 = acc[mm][nn][2] + bb0, v3 = acc[mm][nn][3] + bb1;
                if (phase == 1) {
                    v0 = 0.5f * v0 * (1.0f + erff(v0 * 0.70710678118654752f));
                    v1 = 0.5f * v1 * (1.0f + erff(v1 * 0.70710678118654752f));
                    v2 = 0.5f * v2 * (1.0f + erff(v2 * 0.70710678118654752f));
                    v3 = 0.5f * v3 * (1.0f + erff(v3 * 0.70710678118654752f));
                }
                *(float2*)(stg + row * STG_STRIDE + col) = make_float2(v0, v1);
                *(float2*)(stg + (row + 8) * STG_STRIDE + col) = make_float2(v2, v3);
            }
        }
        __syncthreads();
        {
            int rloc = tid >> 1, q = tid & 1;
            int gr = row0 + rloc;
            if (gr < rend) {
                const float* srow = stg + rloc * STG_STRIDE + q * 32;
                if (phase == 1) {
                    __half* dst = g_hidden + (size_t)gr * DMODEL + n0 + q * 32;
                    #pragma unroll
                    for (int j = 0; j < 4; j++) {
                        float4 aa = ((const float4*)srow)[2 * j];
                        float4 bb = ((const float4*)srow)[2 * j + 1];
                        __half2 h0 = __floats2half2_rn(aa.x, aa.y);
                        __half2 h1 = __floats2half2_rn(aa.z, aa.w);
                        __half2 h2 = __floats2half2_rn(bb.x, bb.y);
                        __half2 h3 = __floats2half2_rn(bb.z, bb.w);
                        ((uint4*)dst)[j] = make_uint4(*(uint32_t*)&h0, *(uint32_t*)&h1,
                                                      *(uint32_t*)&h2, *(uint32_t*)&h3);
                    }
                } else {
                    float* dst = out + (size_t)g_perm[gr] * DMODEL + n0 + q * 32;
                    #pragma unroll
                    for (int j = 0; j < 8; j++)
                        ((float4*)dst)[j] = ((const float4*)srow)[j];
                }
            }
        }
        if (phase == 1) {
            __threadfence();
            __syncthreads();
            if (tid == 0) atomicAdd(&g_done[tile], 1);
        }
        __syncthreads();
    }

    // ---- exit: last CTA resets all state for the next (graph-replayed) run --
    if (tid == 0) {
        __threadfence();
        int ex = atomicAdd(&g_exit, 1);
        *s_jid = (ex == PERSIST_CTAS - 1) ? 1 : 0;
    }
    __syncthreads();
    if (*s_jid) {
        if (tid < MAX_TILES) g_done[tid] = 0;
        if (tid < NEXP) { g_counts[tid] = 0; g_cursor2[tid] = 0; }
        if (tid == 0) {
            g_jobctr = 0; g_gatedone = 0; g_scandone = 0; g_scatterdone = 0;
            g_w1done = 0; g_w2done = 0; g_exit = 0;
        }
        __threadfence();
    }
}

// ---------------- launch -----------------------------------------------------
extern "C" void kernel_launch(void* const* d_in, const int* in_sizes, int n_in,
                              void* d_out, int out_size) {
    const float* x  = (const float*)d_in[0];
    const float* W1 = (const float*)d_in[1];
    const float* b1 = (const float*)d_in[2];
    const float* W2 = (const float*)d_in[3];
    const float* b2 = (const float*)d_in[4];
    const float* Wg = (const float*)d_in[5];
    const float* bg = (const float*)d_in[6];
    float* out = (float*)d_out;

    cudaFuncSetAttribute(mlp_mega, cudaFuncAttributeMaxDynamicSharedMemorySize, SMEM_BYTES);
    mlp_mega<<<PERSIST_CTAS, 256, SMEM_BYTES>>>(x, W1, b1, W2, b2, Wg, bg, out);
}